// round 17
// baseline (speedup 1.0000x reference)
#include <cuda_runtime.h>
#include <cuda_bf16.h>
#include <cuda_fp16.h>
#include <cstdint>
#include <math.h>

#define NN 100000
#define EE 1000000
#define BM 128
#define THREADS 1024
#define NBLK ((NN + BM - 1) / BM)      // 782
#define GRID_PERSIST 148

// conflict-free strides: odd multiples of 16B
#define BP 136                          // B row: 272 B = 17*16
#define XP 264                          // X row: 528 B = 33*16

#define B_BYTES (256 * BP * 2)          // 69632
#define X_BYTES (BM * XP * 2)           // 67584

// smem byte offsets
#define SM_B      0
#define SM_XHI    (B_BYTES)                     // 69632
#define SM_ROWSUM (B_BYTES + X_BYTES)           // 137216 (float[2][128])
#define SM_CTR    (SM_ROWSUM + 1024)            // 138240
#define SM_TOTAL  (SM_CTR + 128)                // 138368

typedef unsigned int u32;
typedef unsigned long long u64;

// Scratch
__device__ int  g_cnt[NN];
__device__ int  g_off[NN];
__device__ int  g_cur[NN];
__device__ int  g_total;
__device__ int  g_meta[EE];                         // src index only
__device__ __align__(16) __half g_Bh[256 * BP];
__device__ __align__(16) __half g_u16[(size_t)NN * 128];  // fp16(norm[s]*ego[s])

// ---------------------------------------------------------------------------
// CSR build: hist + W prep + u16 table prep (fused kernel stays launch #6)
// ---------------------------------------------------------------------------
__global__ void hist_prep_kernel(const int* __restrict__ dst,
                                 int* __restrict__ cnt,
                                 const float* __restrict__ W1,
                                 const float* __restrict__ W2,
                                 const float4* __restrict__ ego4,
                                 const float* __restrict__ norm,
                                 __half* __restrict__ bh,
                                 uint2* __restrict__ u16v)
{
    int e = blockIdx.x * blockDim.x + threadIdx.x;
    int nthr = gridDim.x * blockDim.x;
    if (e < EE) atomicAdd(&cnt[__ldg(dst + e)], 1);
    if (e < 256 * 128) {
        int k = e >> 7;
        int n = e & 127;
        float v = (k < 128) ? __ldg(W1 + k * 128 + n) : __ldg(W2 + (k - 128) * 128 + n);
        bh[k * BP + n] = __float2half_rn(v);
    }
    // u16 table: u16[node][lane*4 .. lane*4+3] = fp16(norm[node] * ego[...])
    for (int idx = e; idx < NN * 32; idx += nthr) {
        int node = idx >> 5;
        float nd = __ldg(norm + node);
        float4 v = __ldg(ego4 + idx);
        u32 p0, p1;
        asm("cvt.rn.f16x2.f32 %0, %1, %2;" : "=r"(p0) : "f"(v.y * nd), "f"(v.x * nd));
        asm("cvt.rn.f16x2.f32 %0, %1, %2;" : "=r"(p1) : "f"(v.w * nd), "f"(v.z * nd));
        u16v[idx] = make_uint2(p0, p1);
    }
}

__global__ void alloc_kernel(const int* __restrict__ cnt,
                             int* __restrict__ off,
                             int* __restrict__ cur,
                             int* __restrict__ total)
{
    int i = blockIdx.x * blockDim.x + threadIdx.x;
    if (i < NN) {
        int o = atomicAdd(total, cnt[i]);
        off[i] = o;
        cur[i] = o;
    }
}

__global__ void scatter_kernel(const int* __restrict__ src,
                               const int* __restrict__ dst,
                               int* __restrict__ cur,
                               int* __restrict__ meta)
{
    int e = blockIdx.x * blockDim.x + threadIdx.x;
    if (e >= EE) return;
    int s = __ldg(src + e);
    int d = __ldg(dst + e);
    int pos = atomicAdd(&cur[d], 1);
    meta[pos] = s;
}

// ---------------------------------------------------------------------------
// PTX helpers
// ---------------------------------------------------------------------------
__device__ __forceinline__ u32 smem_u32_of(const void* p)
{
    u32 a;
    asm("{ .reg .u64 t; cvta.to.shared.u64 t, %1; cvt.u32.u64 %0, t; }"
        : "=r"(a) : "l"(p));
    return a;
}
__device__ __forceinline__ void cp_async16(u32 dst, const void* src)
{
    asm volatile("cp.async.cg.shared.global [%0], [%1], 16;"
                 :: "r"(dst), "l"(src) : "memory");
}
__device__ __forceinline__ void ldsm_x4(u32& r0, u32& r1, u32& r2, u32& r3, u32 addr)
{
    asm volatile("ldmatrix.sync.aligned.m8n8.x4.shared.b16 {%0,%1,%2,%3}, [%4];"
                 : "=r"(r0), "=r"(r1), "=r"(r2), "=r"(r3) : "r"(addr));
}
__device__ __forceinline__ void ldsm_x4_t(u32& r0, u32& r1, u32& r2, u32& r3, u32 addr)
{
    asm volatile("ldmatrix.sync.aligned.m8n8.x4.trans.shared.b16 {%0,%1,%2,%3}, [%4];"
                 : "=r"(r0), "=r"(r1), "=r"(r2), "=r"(r3) : "r"(addr));
}
__device__ __forceinline__ void mma16816(float* c, u32 a0, u32 a1, u32 a2, u32 a3,
                                         u32 b0, u32 b1)
{
    asm volatile(
        "mma.sync.aligned.m16n8k16.row.col.f32.f16.f16.f32 "
        "{%0,%1,%2,%3}, {%4,%5,%6,%7}, {%8,%9}, {%0,%1,%2,%3};"
        : "+f"(c[0]), "+f"(c[1]), "+f"(c[2]), "+f"(c[3])
        : "r"(a0), "r"(a1), "r"(a2), "r"(a3), "r"(b0), "r"(b1));
}
__device__ __forceinline__ void unpack2(u64 v, float& lo, float& hi)
{
    u32 l, h;
    asm("mov.b64 {%0, %1}, %2;" : "=r"(l), "=r"(h) : "l"(v));
    lo = __uint_as_float(l);
    hi = __uint_as_float(h);
}
__device__ __forceinline__ u32 pk16(float lo, float hi)
{
    u32 r;
    asm("cvt.rn.f16x2.f32 %0, %1, %2;" : "=r"(r) : "f"(hi), "f"(lo));
    return r;
}
__device__ __forceinline__ void acc_u16(float4& T, uint2 g)
{
    float2 f0 = __half22float2(*(__half2*)&g.x);
    float2 f1 = __half22float2(*(__half2*)&g.y);
    T.x += f0.x; T.y += f0.y; T.z += f1.x; T.w += f1.y;
}

// ---------------------------------------------------------------------------
// Persistent fused kernel (BM=128): T = sum(u16[s]); S = n_d*T;
// A = ego + S; B = S .* ego; fp16 X x fp16 W mma.sync; work-stealing
// ---------------------------------------------------------------------------
__global__ void __launch_bounds__(THREADS, 1)
fused_kernel(const ulonglong2* __restrict__ egoq,
             const float* __restrict__ norm,
             const int*   __restrict__ off,
             const int*   __restrict__ cnt,
             const int*   __restrict__ meta,
             const uint2* __restrict__ u16v,
             float*       __restrict__ out)
{
    extern __shared__ char smem[];
    const u32 smem_base = smem_u32_of(smem);
    float* rowsum = (float*)(smem + SM_ROWSUM);   // [2][128]
    int*   ctr    = (int*)(smem + SM_CTR);        // [2]

    const int tid  = threadIdx.x;
    const int lane = tid & 31;
    const int warp = tid >> 5;

    // ---- 0) one-time: load B (fp16 W) into smem: 4352 x 16B chunks
    {
        const char* sb = (const char*)g_Bh;
        #pragma unroll
        for (int i = 0; i < 5; ++i) {
            int m = tid + i * THREADS;
            if (m < 4352) cp_async16(smem_base + SM_B + m * 16, sb + m * 16);
        }
        asm volatile("cp.async.commit_group;" ::: "memory");
        asm volatile("cp.async.wait_group 0;" ::: "memory");
    }
    if (tid < 2 * BM) rowsum[tid] = 0.f;
    if (tid < 2) ctr[tid] = 0;
    __syncthreads();

    // GEMM constants: warp grid 8m x 4n; warp tile 16m x 32n
    const int m0 = (warp >> 2) * 16;
    const int n0 = (warp & 3) * 32;
    const u32 a_row = m0 + (lane & 15);
    const u32 a_col = (lane >> 4) * 8;
    const u32 aBase = smem_base + SM_XHI + a_row * (XP * 2) + a_col * 2;
    const u32 b_krow = (lane & 7) + ((lane >> 3) & 1) * 8;
    const u32 b_ncol = (lane >> 4) * 8;
    const u32 bBase = smem_base + SM_B + b_krow * (BP * 2) + (n0 + b_ncol) * 2;
    const int r0 = m0 + (lane >> 2);
    const int r1 = r0 + 8;

    int par = 0;
    for (int tile = blockIdx.x; tile < NBLK; tile += GRID_PERSIST, par ^= 1) {
        const int rowBase = tile * BM;

        // ---- 1) aggregate: T = sum(u16[s]); steal nodes until exhausted
        for (;;) {
            int r;
            if (lane == 0) r = atomicAdd(&ctr[par], 1);
            r = __shfl_sync(0xffffffffu, r, 0);
            if (r >= BM) break;

            int node = rowBase + r;
            bool valid = node < NN;

            ulonglong2 hd2 = valid ? __ldg(egoq + (size_t)node * 32 + lane)
                                   : make_ulonglong2(0ull, 0ull);
            float nd = valid ? __ldg(norm + node) : 0.f;
            float4 T = make_float4(0.f, 0.f, 0.f, 0.f);

            int n  = valid ? __ldg(cnt + node) : 0;
            int e0 = valid ? __ldg(off + node) : 0;

            for (int c = 0; c < n; c += 32) {
                int lim = min(32, n - c);
                int mm = (lane < lim) ? __ldg(meta + e0 + c + lane) : 0;
                int nb = lim & ~3;
                uint2 g[4];
                if (nb) {
                    #pragma unroll
                    for (int t = 0; t < 4; ++t) {
                        int s = __shfl_sync(0xffffffffu, mm, t);
                        g[t] = __ldg(u16v + (size_t)s * 32 + lane);
                    }
                }
                for (int j = 0; j < nb; j += 4) {
                    uint2 c0 = g[0], c1 = g[1], c2 = g[2], c3 = g[3];
                    if (j + 4 < nb) {
                        #pragma unroll
                        for (int t = 0; t < 4; ++t) {
                            int s = __shfl_sync(0xffffffffu, mm, j + 4 + t);
                            g[t] = __ldg(u16v + (size_t)s * 32 + lane);
                        }
                    }
                    acc_u16(T, c0);
                    acc_u16(T, c1);
                    acc_u16(T, c2);
                    acc_u16(T, c3);
                }
                for (int j = nb; j < lim; ++j) {
                    int s = __shfl_sync(0xffffffffu, mm, j);
                    uint2 g0 = __ldg(u16v + (size_t)s * 32 + lane);
                    acc_u16(T, g0);
                }
            }

            // S = nd*T; A = ego + S; Bpart = S .* ego
            float hx, hy, hz, hw;
            unpack2(hd2.x, hx, hy);
            unpack2(hd2.y, hz, hw);
            float sx = nd * T.x, sy = nd * T.y, sz = nd * T.z, sw = nd * T.w;

            uint4 xv;
            xv.x = pk16(hx + sx, hy + sy);
            xv.y = pk16(hz + sz, hw + sw);
            xv.z = pk16(sx * hx, sy * hy);
            xv.w = pk16(sz * hz, sw * hw);

            uint2* xh = (uint2*)(smem + SM_XHI + (size_t)r * (XP * 2));
            xh[lane]      = make_uint2(xv.x, xv.y);
            xh[32 + lane] = make_uint2(xv.z, xv.w);
        }
        __syncthreads();                 // bar1: X complete

        if (tid == 0) ctr[par ^ 1] = 0;
        if (tid < BM) rowsum[(par ^ 1) * BM + tid] = 0.f;

        // ---- 2) GEMM: warp tile 16m x 32n; K=256; single term
        float acc[4][4];
        #pragma unroll
        for (int i = 0; i < 4; ++i)
            #pragma unroll
            for (int j = 0; j < 4; ++j) acc[i][j] = 0.f;

        #pragma unroll 4
        for (int ks = 0; ks < 16; ++ks) {
            const u32 kOffA = ks * 32;
            const u32 kOffB = ks * 16 * (BP * 2);
            u32 a0, a1, a2, a3;
            ldsm_x4(a0, a1, a2, a3, aBase + kOffA);

            u32 b0, b1, b2, b3, b4, b5, b6, b7;
            ldsm_x4_t(b0, b1, b2, b3, bBase + kOffB);
            ldsm_x4_t(b4, b5, b6, b7, bBase + kOffB + 32);
            mma16816(acc[0], a0, a1, a2, a3, b0, b1);
            mma16816(acc[1], a0, a1, a2, a3, b2, b3);
            mma16816(acc[2], a0, a1, a2, a3, b4, b5);
            mma16816(acc[3], a0, a1, a2, a3, b6, b7);
        }

        // ---- 3) leaky relu + per-row sumsq partials
        float p0 = 0.f, p1 = 0.f;
        #pragma unroll
        for (int nt = 0; nt < 4; ++nt) {
            #pragma unroll
            for (int j = 0; j < 4; ++j) {
                float v = acc[nt][j];
                v = (v >= 0.f) ? v : 0.2f * v;
                acc[nt][j] = v;
                if (j < 2) p0 = fmaf(v, v, p0);
                else       p1 = fmaf(v, v, p1);
            }
        }
        p0 += __shfl_xor_sync(0xffffffffu, p0, 1);
        p0 += __shfl_xor_sync(0xffffffffu, p0, 2);
        p1 += __shfl_xor_sync(0xffffffffu, p1, 1);
        p1 += __shfl_xor_sync(0xffffffffu, p1, 2);
        if ((lane & 3) == 0) {
            atomicAdd(rowsum + par * BM + r0, p0);
            atomicAdd(rowsum + par * BM + r1, p1);
        }
        __syncthreads();                 // bar2: rowsum complete, X reads done

        // ---- 4) scale + store
        const float inv0 = 1.0f / fmaxf(sqrtf(rowsum[par * BM + r0]), 1e-12f);
        const float inv1 = 1.0f / fmaxf(sqrtf(rowsum[par * BM + r1]), 1e-12f);
        float2* out2 = (float2*)out;
        const int g0 = rowBase + r0;
        const int g1 = rowBase + r1;
        const int colh = (n0 + (lane & 3) * 2) >> 1;
        #pragma unroll
        for (int nt = 0; nt < 4; ++nt) {
            int c2 = colh + nt * 4;
            if (g0 < NN)
                out2[(size_t)g0 * 64 + c2] = make_float2(acc[nt][0] * inv0, acc[nt][1] * inv0);
            if (g1 < NN)
                out2[(size_t)g1 * 64 + c2] = make_float2(acc[nt][2] * inv1, acc[nt][3] * inv1);
        }
    }
}

// ---------------------------------------------------------------------------
// Launch
// ---------------------------------------------------------------------------
extern "C" void kernel_launch(void* const* d_in, const int* in_sizes, int n_in,
                              void* d_out, int out_size)
{
    const float* ego  = (const float*)d_in[0];
    const float* norm = (const float*)d_in[1];
    const int*   src  = (const int*)d_in[2];
    const int*   dst  = (const int*)d_in[3];
    const float* W1   = (const float*)d_in[4];
    const float* W2   = (const float*)d_in[5];
    float* out = (float*)d_out;

    int*  cnt;   cudaGetSymbolAddress((void**)&cnt,   g_cnt);
    int*  off;   cudaGetSymbolAddress((void**)&off,   g_off);
    int*  cur;   cudaGetSymbolAddress((void**)&cur,   g_cur);
    int*  total; cudaGetSymbolAddress((void**)&total, g_total);
    int*  meta;  cudaGetSymbolAddress((void**)&meta,  g_meta);
    __half* bh;  cudaGetSymbolAddress((void**)&bh,    g_Bh);
    __half* u16; cudaGetSymbolAddress((void**)&u16,   g_u16);

    cudaMemsetAsync(cnt, 0, NN * sizeof(int));
    cudaMemsetAsync(total, 0, sizeof(int));
    hist_prep_kernel<<<(EE + 255) / 256, 256>>>(
        dst, cnt, W1, W2, (const float4*)ego, norm, bh, (uint2*)u16);
    alloc_kernel<<<(NN + 255) / 256, 256>>>(cnt, off, cur, total);
    scatter_kernel<<<(EE + 255) / 256, 256>>>(src, dst, cur, meta);

    cudaFuncSetAttribute(fused_kernel,
                         cudaFuncAttributeMaxDynamicSharedMemorySize, SM_TOTAL);
    fused_kernel<<<GRID_PERSIST, THREADS, SM_TOTAL>>>(
        (const ulonglong2*)ego, norm, off, cnt, meta, (const uint2*)u16, out);
}